// round 17
// baseline (speedup 1.0000x reference)
#include <cuda_runtime.h>
#include <cuda_bf16.h>

// UmbralCone: hyperbolic cone distance.  (warp-per-row, zero-SMEM version)
//  weight: f32 [100000, 32] (d_in[0]);  inputs: i32 [16384, 50] (d_in[1])
//  out: f32 [16384, 49]
//
// One warp per batch row; no shared memory, no barriers, no cp.async.
// The previous designs all streamed ~105MB through SMEM twice (STS+LDS);
// at 128 B/cy/SM that crossbar time (~17us chip-wide) matches the observed
// plateau exactly. Here children go gmem->registers via coalesced LDG.128
// (8 lanes per 128B row, 4 rows per inst) and dot/norm are reduced with
// xor-butterflies inside each 8-lane group. Sweep s parks its 4 results on
// lanes l&7==s, giving the bijection c = 4*(l&7) + (l>>3) so that all 32
// lanes run the transcendental tail in parallel (49 children = 32 + 17).

#define KTOT 50
#define NCH  49
#define WPB  8      // warps per block

// a = (inv_np, sin_beta, cos_beta, hp); b = (2*scale, nps2, 2/(1-nps2), 0)
__device__ __forceinline__ void parent_scalars(float np2, float4& a, float4& b) {
    const float SINH_R = 0.10016675001984403f;   // sinh(0.1)
    const float COSH_R = 1.0050041680558035f;    // cosh(0.1)
    const float EK     = 1.0100501670841680f;    // exp(0.01)
    float np      = sqrtf(np2);
    float inv_np  = __fdividef(1.0f, np);
    float sin_beta = SINH_R * 0.5f * (1.0f - np2) * inv_np;
    float cos_beta = sqrtf(fmaxf(1.0f - sin_beta * sin_beta, 0.0f));
    float zp = fmaxf(COSH_R * __fdividef(1.0f - np2, 1.0f + np2), 1.0f + 1e-7f);
    float hp = __logf(zp + sqrtf(zp * zp - 1.0f));   // arcosh
    float tmp   = __fdividef(1.0f + np, 1.0f - np);
    float ektmp = EK * tmp;
    float scale = __fdividef(ektmp - 1.0f, (ektmp + 1.0f) * np);
    float nps2  = scale * scale * np2;
    float w2    = __fdividef(2.0f, 1.0f - nps2);
    a = make_float4(inv_np, sin_beta, cos_beta, hp);
    b = make_float4(2.0f * scale, nps2, w2, 0.0f);
}

__device__ __forceinline__ float pair_tail(float nc2, float dot, float4 a, float4 b) {
    float inv_nc = rsqrtf(nc2);
    float nc     = nc2 * inv_nc;
    float ca = dot * a.x * inv_nc;
    ca = fminf(fmaxf(ca, -1.0f + 1e-7f), 1.0f - 1e-7f);
    float sa = sqrtf(1.0f - ca * ca);            // sin(alpha)
    float sin_theta = sa * a.z - ca * a.y;       // sin(alpha - beta)
    float temp = 2.0f * nc * sin_theta;
    float omn     = 1.0f - nc2;
    float inv_omn = __fdividef(1.0f, omn);
    float hc = (1.0f + nc2) * rsqrtf(fmaf(omn, omn, temp * temp));
    bool  up = (a.w - hc) > 0.0f;                // altitude > 0
    // Merged arcosh/asinh: both are log(A + sqrt(A*A + s)).
    float diff2 = fmaf(-b.x, dot, nc2 + b.y);            // |c - s*p|^2
    float z = fmaf(b.z * diff2, inv_omn, 1.0f);          // arcosh arg
    float x = temp * inv_omn;                            // asinh arg
    float A   = up ? fmaxf(z, 1.0f + 1e-7f) : fabsf(x);
    float sgn = up ? -1.0f : 1.0f;
    float val = __logf(A + sqrtf(fmaf(A, A, sgn)));
    return up ? val : copysignf(val, x) + 0.1f;          // +RADIUS
}

__global__ __launch_bounds__(32 * WPB, 6)
void umbral_warp_kernel(const float* __restrict__ weight,
                        const int* __restrict__ inputs,
                        float* __restrict__ out,
                        int B) {
    const int l   = threadIdx.x & 31;
    const int wid = threadIdx.x >> 5;
    const int b   = blockIdx.x * WPB + wid;
    if (b >= B) return;

    const int base = b * KTOT;
    const int fi   = l & 7;        // float4 slice within a 128B row
    const int g    = l >> 3;       // 8-lane group id (0..3)
    const unsigned FULL = 0xffffffffu;

    const float4* w4 = (const float4*)weight;

    // ---- indices: children 0..31 on lanes 0..31; 32..48 on lanes 0..16 ----
    int idxA = inputs[base + 1 + l];
    int idxB = (l < NCH - 32) ? inputs[base + 33 + l] : 0;   // 0 = safe dummy row
    int pidx = inputs[base];

    // ---- parent slice + np2 (butterfly over the 8-lane group) ----
    float4 ps = w4[pidx * 8 + fi];
    float np2 = fmaf(ps.x, ps.x, fmaf(ps.y, ps.y, fmaf(ps.z, ps.z, ps.w * ps.w)));
    np2 += __shfl_xor_sync(FULL, np2, 1);
    np2 += __shfl_xor_sync(FULL, np2, 2);
    np2 += __shfl_xor_sync(FULL, np2, 4);

    float4 pa, pb;
    parent_scalars(np2, pa, pb);   // redundant across lanes, no divergence

    // ---- 13 sweeps x 4 children; results parked per-lane ----
    float nc2_1 = 1.0f, dot_1 = 0.0f;   // round 1: children 0..31
    float nc2_2 = 1.0f, dot_2 = 0.0f;   // round 2: children 32..48
    #pragma unroll
    for (int s = 0; s < 13; s++) {
        int src = 4 * s + g;                          // child id this group handles
        int cid = (s < 8) ? __shfl_sync(FULL, idxA, src)
                          : __shfl_sync(FULL, idxB, src - 32);
        float4 cv = w4[cid * 8 + fi];                 // coalesced: 4 lines / inst
        float ncp = fmaf(cv.x, cv.x, fmaf(cv.y, cv.y, fmaf(cv.z, cv.z, cv.w * cv.w)));
        float dp  = fmaf(ps.x, cv.x, fmaf(ps.y, cv.y, fmaf(ps.z, cv.z, ps.w * cv.w)));
        ncp += __shfl_xor_sync(FULL, ncp, 1);
        dp  += __shfl_xor_sync(FULL, dp,  1);
        ncp += __shfl_xor_sync(FULL, ncp, 2);
        dp  += __shfl_xor_sync(FULL, dp,  2);
        ncp += __shfl_xor_sync(FULL, ncp, 4);
        dp  += __shfl_xor_sync(FULL, dp,  4);
        if (s < 8) {
            if (fi == s)     { nc2_1 = ncp; dot_1 = dp; }
        } else {
            if (fi == s - 8) { nc2_2 = ncp; dot_2 = dp; }
        }
    }

    // ---- tails: all 32 lanes in parallel ----
    // round 1: child c1 = 4*fi + g  (bijection onto 0..31)
    const int c1 = 4 * fi + g;
    out[b * NCH + c1] = pair_tail(nc2_1, dot_1, pa, pb);

    // round 2: child c2 = 32 + 4*fi + g, valid lanes: fi<5 && c2<49
    const int c2 = 32 + 4 * fi + g;
    if (fi < 5 && c2 < NCH)
        out[b * NCH + c2] = pair_tail(nc2_2, dot_2, pa, pb);
}

extern "C" void kernel_launch(void* const* d_in, const int* in_sizes, int n_in,
                              void* d_out, int out_size) {
    const float* weight = (const float*)d_in[0];
    const int*   inputs = (const int*)d_in[1];
    float*       out    = (float*)d_out;

    int B = in_sizes[1] / KTOT;              // 16384
    int grid = (B + WPB - 1) / WPB;          // 2048

    umbral_warp_kernel<<<grid, 32 * WPB>>>(weight, inputs, out, B);
}